// round 14
// baseline (speedup 1.0000x reference)
#include <cuda_runtime.h>
#include <math.h>

#define N_NODES 50000
#define N_EDGES 800000
#define F_IN    11
#define HID     128
#define HEADS   4
#define CDIM    32
#define NLAYERS 4

// ---------------- scratch (device globals; no allocation allowed) ----------
__device__ float g_x [N_NODES * HID];
__device__ float g_xl[N_NODES * HID];
__device__ float g_xr[N_NODES * HID];
__device__ int   g_rowptr[N_NODES + 1];
__device__ int   g_cnt[N_NODES];
__device__ int   g_csr_src[N_EDGES];

#define SCAN_BLK   512
#define NSCAN_BLKS ((N_NODES + SCAN_BLK - 1) / SCAN_BLK)   // 98
__device__ int g_bsum[NSCAN_BLKS];

// ---------------- f32x2 packed math helpers --------------------------------
__device__ __forceinline__ unsigned long long pack2(float x, float y) {
    unsigned long long r;
    asm("mov.b64 %0, {%1, %2};" : "=l"(r) : "f"(x), "f"(y));
    return r;
}
__device__ __forceinline__ float2 unpack2(unsigned long long v) {
    float2 r;
    asm("mov.b64 {%0, %1}, %2;" : "=f"(r.x), "=f"(r.y) : "l"(v));
    return r;
}
__device__ __forceinline__ void ffma2(unsigned long long& d,
                                      unsigned long long a,
                                      unsigned long long b) {
    asm("fma.rn.f32x2 %0, %1, %2, %0;" : "+l"(d) : "l"(a), "l"(b));
}

// ---------------- embedding: x = relu(nf @ W_emb^T + b_emb) ----------------
__global__ void embed_kernel(const float* __restrict__ nf,
                             const float* __restrict__ Wemb,
                             const float* __restrict__ bemb) {
    int tid = blockIdx.x * blockDim.x + threadIdx.x;
    if (tid >= N_NODES * HID) return;
    int node = tid >> 7;
    int col  = tid & 127;
    const float* xrow = nf + node * F_IN;
    const float* wrow = Wemb + col * F_IN;
    float a = bemb[col];
#pragma unroll
    for (int i = 0; i < F_IN; i++) a += xrow[i] * wrow[i];
    g_x[tid] = fmaxf(a, 0.f);
}

// ---------------- CSR build ------------------------------------------------
__global__ void zero_cnt_out_kernel(float* out) {
    int i = blockIdx.x * blockDim.x + threadIdx.x;
    if (i < N_NODES) g_cnt[i] = 0;
    if (i < 2 * HID) out[i] = 0.f;   // mean accum + max accum (x >= 0)
}

__global__ void zero_cnt_kernel() {
    int i = blockIdx.x * blockDim.x + threadIdx.x;
    if (i < N_NODES) g_cnt[i] = 0;
}

__global__ void count_kernel(const int* __restrict__ ei) {
    int e = blockIdx.x * blockDim.x + threadIdx.x;
    if (e < N_EDGES) atomicAdd(&g_cnt[ei[N_EDGES + e]], 1);
}

__device__ __forceinline__ int warp_incl_scan(int v) {
    int lane = threadIdx.x & 31;
#pragma unroll
    for (int off = 1; off < 32; off <<= 1) {
        int n = __shfl_up_sync(0xFFFFFFFFu, v, off);
        if (lane >= off) v += n;
    }
    return v;
}

__global__ void blocksum_kernel() {
    __shared__ int ws[SCAN_BLK / 32];
    int i = blockIdx.x * SCAN_BLK + threadIdx.x;
    int v = (i < N_NODES) ? g_cnt[i] : 0;
#pragma unroll
    for (int off = 16; off > 0; off >>= 1) v += __shfl_xor_sync(0xFFFFFFFFu, v, off);
    if ((threadIdx.x & 31) == 0) ws[threadIdx.x >> 5] = v;
    __syncthreads();
    if (threadIdx.x < 32) {
        int t = (threadIdx.x < SCAN_BLK / 32) ? ws[threadIdx.x] : 0;
#pragma unroll
        for (int off = 8; off > 0; off >>= 1) t += __shfl_xor_sync(0xFFFFFFFFu, t, off);
        if (threadIdx.x == 0) g_bsum[blockIdx.x] = t;
    }
}

__global__ void bsum_scan_kernel() {   // 1 block, 128 threads, scans 98 values
    __shared__ int ws[4];
    int tid = threadIdx.x;
    int v = (tid < NSCAN_BLKS) ? g_bsum[tid] : 0;
    int incl = warp_incl_scan(v);
    if ((tid & 31) == 31) ws[tid >> 5] = incl;
    __syncthreads();
    if (tid < 32) {
        int t = (tid < 4) ? ws[tid] : 0;
        t = warp_incl_scan(t);
        if (tid < 4) ws[tid] = t;
    }
    __syncthreads();
    int wid = tid >> 5;
    int excl = (wid ? ws[wid - 1] : 0) + incl - v;
    if (tid < NSCAN_BLKS) g_bsum[tid] = excl;
}

__global__ void rowptr_kernel() {
    __shared__ int ws[SCAN_BLK / 32];
    int tid = threadIdx.x;
    int i = blockIdx.x * SCAN_BLK + tid;
    int v = (i < N_NODES) ? g_cnt[i] : 0;
    int incl = warp_incl_scan(v);
    int wid = tid >> 5;
    if ((tid & 31) == 31) ws[wid] = incl;
    __syncthreads();
    if (tid < 32) {
        int t = (tid < SCAN_BLK / 32) ? ws[tid] : 0;
        t = warp_incl_scan(t);
        if (tid < SCAN_BLK / 32) ws[tid] = t;
    }
    __syncthreads();
    int base = g_bsum[blockIdx.x] + (wid ? ws[wid - 1] : 0);
    int excl = base + incl - v;
    if (i < N_NODES)      g_rowptr[i] = excl;
    if (i == N_NODES - 1) g_rowptr[N_NODES] = excl + v;
}

__global__ void scatter_kernel(const int* __restrict__ ei) {
    int e = blockIdx.x * blockDim.x + threadIdx.x;
    if (e >= N_EDGES) return;
    int src = ei[e];
    int dst = ei[N_EDGES + e];
    int pos = g_rowptr[dst] + atomicAdd(&g_cnt[dst], 1);
    g_csr_src[pos] = src;
}

// ---------------- node transform (quarter per CTA): xo[:,cols] = x@W^T + b -
// CTA: 64 nodes x 64 output cols. blockIdx.y: bit0 = L/R, bit1 = col half.
// smem 67.6KB -> 3 CTAs/SM (24 warps). Lane owns 2 cols (1 f32x2 acc/node).
#define BN        64
#define WQ_STRIDE 68
#define TF_SMEM   ((128 * WQ_STRIDE + BN * HID) * 4)   // 67584 bytes

__global__ __launch_bounds__(256, 3)
void transform_quarter_kernel(const float* __restrict__ Wlg,
                              const float* __restrict__ blg,
                              const float* __restrict__ Wrg,
                              const float* __restrict__ brg) {
    extern __shared__ float smem[];
    float* sW = smem;                       // [128 k][WQ_STRIDE]  sW[k][o_local]
    float* sx = smem + 128 * WQ_STRIDE;     // [BN][128]

    int m  = blockIdx.y & 1;                // 0 = L, 1 = R
    int ch = blockIdx.y >> 1;               // col half
    const float* Wg = (m ? Wrg : Wlg) + ch * 64 * HID;
    const float* bg = (m ? brg : blg) + ch * 64;
    float* xo = (m ? g_xr : g_xl) + ch * 64;

    int nbase = blockIdx.x * BN;
    // stage W half transposed: sW[k][o] = Wg[o][k]
    for (int idx = threadIdx.x; idx < 64 * HID; idx += 256) {
        int o = idx >> 7, k = idx & 127;
        sW[k * WQ_STRIDE + o] = Wg[idx];
    }
    for (int idx = threadIdx.x; idx < BN * HID; idx += 256) {
        int node = nbase + (idx >> 7);
        sx[idx] = (node < N_NODES) ? g_x[node * HID + (idx & 127)] : 0.f;
    }
    __syncthreads();

    int lane = threadIdx.x & 31;
    int wrp  = threadIdx.x >> 5;
    int col  = lane * 2;                    // local col pair
    int n0   = wrp * 8;

    unsigned long long acc[8];
#pragma unroll
    for (int j = 0; j < 8; j++) acc[j] = 0ull;

    for (int kq = 0; kq < 128; kq += 4) {
        float4 xq[8];
#pragma unroll
        for (int j = 0; j < 8; j++)
            xq[j] = *reinterpret_cast<const float4*>(&sx[(n0 + j) * HID + kq]);
        const float* xs = reinterpret_cast<const float*>(xq);
#pragma unroll
        for (int kk = 0; kk < 4; kk++) {
            int k = kq + kk;
            unsigned long long w =
                *reinterpret_cast<const unsigned long long*>(&sW[k * WQ_STRIDE + col]);
#pragma unroll
            for (int j = 0; j < 8; j++) {
                float xv = xs[j * 4 + kk];
                ffma2(acc[j], pack2(xv, xv), w);
            }
        }
    }

    float2 b2 = *reinterpret_cast<const float2*>(&bg[col]);
#pragma unroll
    for (int j = 0; j < 8; j++) {
        int node = nbase + n0 + j;
        if (node < N_NODES) {
            float2 a = unpack2(acc[j]);
            float2 o = {a.x + b2.x, a.y + b2.y};
            *reinterpret_cast<float2*>(&xo[(size_t)node * HID + col]) = o;
        }
    }
}

// ---------------- GATv2 aggregation: warp/node, dual-stream online softmax -
// lane = h*8 + i; lane owns channels [h*32 + i*4 .. +3] as float4.
__global__ __launch_bounds__(256)
void gat_agg_kernel(const float* __restrict__ att,
                    const float* __restrict__ bias,
                    int layer) {
    int warp = (blockIdx.x * blockDim.x + threadIdx.x) >> 5;
    int lane = threadIdx.x & 31;
    if (warp >= N_NODES) return;
    int node = warp;
    int h = lane >> 3;
    int i4 = (lane & 7) * 4;
    int chan = h * CDIM + i4;
    int base = node * HID + chan;

    float4 xr4 = *reinterpret_cast<const float4*>(&g_xr[base]);
    float4 at4 = *reinterpret_cast<const float4*>(&att[layer * HID + chan]);

    int beg = g_rowptr[node], end = g_rowptr[node + 1];
    int deg = end - beg;
    int nA  = (deg + 1) >> 1;
    int pB0 = beg + nA;

    float4 accA = {0,0,0,0}, accB = {0,0,0,0};
    float dA = 0.f, dB = 0.f, mA = -1e30f, mB = -1e30f;
    float4 xA = {0,0,0,0}, xB = {0,0,0,0};
    if (deg > 0)   xA = *reinterpret_cast<const float4*>(&g_xl[g_csr_src[beg] * HID + chan]);
    if (pB0 < end) xB = *reinterpret_cast<const float4*>(&g_xl[g_csr_src[pB0] * HID + chan]);
    const float NEG_INF = __int_as_float(0xff800000);

    for (int i = 0; i < nA; i++) {
        float4 cA = xA, cB = xB;
        bool hasB = (pB0 + i) < end;
        if (i + 1 < nA)        xA = *reinterpret_cast<const float4*>(&g_xl[g_csr_src[beg + i + 1] * HID + chan]);
        if (pB0 + i + 1 < end) xB = *reinterpret_cast<const float4*>(&g_xl[g_csr_src[pB0 + i + 1] * HID + chan]);

        float a0 = cA.x + xr4.x, a1 = cA.y + xr4.y, a2 = cA.z + xr4.z, a3 = cA.w + xr4.w;
        float b0 = cB.x + xr4.x, b1 = cB.y + xr4.y, b2 = cB.z + xr4.z, b3 = cB.w + xr4.w;
        a0 = (a0 > 0.f) ? a0 : 0.2f * a0;  b0 = (b0 > 0.f) ? b0 : 0.2f * b0;
        a1 = (a1 > 0.f) ? a1 : 0.2f * a1;  b1 = (b1 > 0.f) ? b1 : 0.2f * b1;
        a2 = (a2 > 0.f) ? a2 : 0.2f * a2;  b2 = (b2 > 0.f) ? b2 : 0.2f * b2;
        a3 = (a3 > 0.f) ? a3 : 0.2f * a3;  b3 = (b3 > 0.f) ? b3 : 0.2f * b3;
        float la = a0 * at4.x + a1 * at4.y + a2 * at4.z + a3 * at4.w;
        float lb = b0 * at4.x + b1 * at4.y + b2 * at4.z + b3 * at4.w;
        la += __shfl_xor_sync(0xFFFFFFFFu, la, 4);
        lb += __shfl_xor_sync(0xFFFFFFFFu, lb, 4);
        la += __shfl_xor_sync(0xFFFFFFFFu, la, 2);
        lb += __shfl_xor_sync(0xFFFFFFFFu, lb, 2);
        la += __shfl_xor_sync(0xFFFFFFFFu, la, 1);
        lb += __shfl_xor_sync(0xFFFFFFFFu, lb, 1);
        lb = hasB ? lb : NEG_INF;

        float nmA = fmaxf(mA, la);
        float scA = __expf(mA - nmA);
        float pa  = __expf(la - nmA);
        dA = dA * scA + pa;
        accA.x = accA.x * scA + pa * cA.x;
        accA.y = accA.y * scA + pa * cA.y;
        accA.z = accA.z * scA + pa * cA.z;
        accA.w = accA.w * scA + pa * cA.w;
        mA = nmA;

        float nmB = fmaxf(mB, lb);
        float scB = __expf(mB - nmB);
        float pb  = __expf(lb - nmB);
        dB = dB * scB + pb;
        accB.x = accB.x * scB + pb * cB.x;
        accB.y = accB.y * scB + pb * cB.y;
        accB.z = accB.z * scB + pb * cB.z;
        accB.w = accB.w * scB + pb * cB.w;
        mB = nmB;
    }

    // merge streams
    float nm = fmaxf(mA, mB);
    float sA = __expf(mA - nm), sB = __expf(mB - nm);
    float den = dA * sA + dB * sB;
    float4 acc;
    acc.x = accA.x * sA + accB.x * sB;
    acc.y = accA.y * sA + accB.y * sB;
    acc.z = accA.z * sA + accB.z * sB;
    acc.w = accA.w * sA + accB.w * sB;

    float inv = (den > 0.f) ? 1.f / den : 0.f;
    float4 b4 = *reinterpret_cast<const float4*>(&bias[layer * HID + chan]);
    float4 o;
    o.x = fmaxf(acc.x * inv + b4.x, 0.f);
    o.y = fmaxf(acc.y * inv + b4.y, 0.f);
    o.z = fmaxf(acc.z * inv + b4.z, 0.f);
    o.w = fmaxf(acc.w * inv + b4.w, 0.f);
    if (layer > 0) {
        float4 prev = *reinterpret_cast<const float4*>(&g_x[base]);
        o.x += prev.x; o.y += prev.y; o.z += prev.z; o.w += prev.w;
    }
    *reinterpret_cast<float4*>(&g_x[base]) = o;
}

// ---------------- epilogue: graph embedding + x copy (fused) ---------------
__global__ void reduce2_kernel(float* __restrict__ out) {
    int col = threadIdx.x;   // 128 threads
    float s = 0.f, mx = 0.f;
    for (int r = blockIdx.x; r < N_NODES; r += gridDim.x) {
        float v = g_x[r * HID + col];
        s += v;
        mx = fmaxf(mx, v);
        out[2 * HID + r * HID + col] = v;
    }
    atomicAdd(&out[col], s * (1.0f / N_NODES));
    atomicMax(reinterpret_cast<int*>(out) + HID + col, __float_as_int(mx));  // x >= 0
}

// ---------------- launch ---------------------------------------------------
extern "C" void kernel_launch(void* const* d_in, const int* in_sizes, int n_in,
                              void* d_out, int out_size) {
    const float* nf   = (const float*)d_in[0];
    const int*   ei   = (const int*)  d_in[1];
    const float* Wemb = (const float*)d_in[3];
    const float* bemb = (const float*)d_in[4];
    const float* Wl   = (const float*)d_in[5];
    const float* bl   = (const float*)d_in[6];
    const float* Wr   = (const float*)d_in[7];
    const float* br   = (const float*)d_in[8];
    const float* att  = (const float*)d_in[9];
    const float* bias = (const float*)d_in[10];
    float* out = (float*)d_out;

    cudaFuncSetAttribute(transform_quarter_kernel,
                         cudaFuncAttributeMaxDynamicSharedMemorySize, TF_SMEM);

    dim3 tf_grid((N_NODES + BN - 1) / BN, 4);

    // transform kernel at launch slot #4 so the fixed "-s 5 -c 1" ncu capture
    // lands on the dominant kernel.
    embed_kernel<<<(N_NODES * HID + 255) / 256, 256>>>(nf, Wemb, bemb);          // 1
    zero_cnt_out_kernel<<<(N_NODES + 255) / 256, 256>>>(out);                    // 2
    count_kernel<<<(N_EDGES + 255) / 256, 256>>>(ei);                            // 3
    transform_quarter_kernel<<<tf_grid, 256, TF_SMEM>>>(Wl, bl, Wr, br);         // 4 (layer 0)
    blocksum_kernel<<<NSCAN_BLKS, SCAN_BLK>>>();                                 // 5
    bsum_scan_kernel<<<1, 128>>>();                                              // 6
    rowptr_kernel<<<NSCAN_BLKS, SCAN_BLK>>>();                                   // 7
    zero_cnt_kernel<<<(N_NODES + 255) / 256, 256>>>();                           // 8
    scatter_kernel<<<(N_EDGES + 255) / 256, 256>>>(ei);                          // 9

    // GATv2 layers
    for (int l = 0; l < NLAYERS; l++) {
        if (l > 0)
            transform_quarter_kernel<<<tf_grid, 256, TF_SMEM>>>(
                Wl + l * HID * HID, bl + l * HID, Wr + l * HID * HID, br + l * HID);
        gat_agg_kernel<<<(N_NODES * 32 + 255) / 256, 256>>>(att, bias, l);
    }

    // outputs: [graph_mean(128) | graph_max(128) | x(50000*128)]
    reduce2_kernel<<<1024, HID>>>(out);
}

// round 15
// speedup vs baseline: 1.4708x; 1.4708x over previous
#include <cuda_runtime.h>
#include <math.h>

#define N_NODES 50000
#define N_EDGES 800000
#define F_IN    11
#define HID     128
#define HEADS   4
#define CDIM    32
#define NLAYERS 4

// ---------------- scratch (device globals; no allocation allowed) ----------
__device__ float g_x [N_NODES * HID];
__device__ float g_xl[N_NODES * HID];
__device__ float g_xr[N_NODES * HID];
__device__ int   g_rowptr[N_NODES + 1];
__device__ int   g_cnt[N_NODES];
__device__ int   g_csr_src[N_EDGES];

#define SCAN_BLK   512
#define NSCAN_BLKS ((N_NODES + SCAN_BLK - 1) / SCAN_BLK)   // 98
__device__ int g_bsum[NSCAN_BLKS];

// ---------------- f32x2 packed math helpers --------------------------------
__device__ __forceinline__ unsigned long long pack2(float x, float y) {
    unsigned long long r;
    asm("mov.b64 %0, {%1, %2};" : "=l"(r) : "f"(x), "f"(y));
    return r;
}
__device__ __forceinline__ float2 unpack2(unsigned long long v) {
    float2 r;
    asm("mov.b64 {%0, %1}, %2;" : "=f"(r.x), "=f"(r.y) : "l"(v));
    return r;
}
__device__ __forceinline__ void ffma2(unsigned long long& d,
                                      unsigned long long a,
                                      unsigned long long b) {
    asm("fma.rn.f32x2 %0, %1, %2, %0;" : "+l"(d) : "l"(a), "l"(b));
}

// ---------------- embedding: x = relu(nf @ W_emb^T + b_emb) ----------------
__global__ void embed_kernel(const float* __restrict__ nf,
                             const float* __restrict__ Wemb,
                             const float* __restrict__ bemb) {
    int tid = blockIdx.x * blockDim.x + threadIdx.x;
    if (tid >= N_NODES * HID) return;
    int node = tid >> 7;
    int col  = tid & 127;
    const float* xrow = nf + node * F_IN;
    const float* wrow = Wemb + col * F_IN;
    float a = bemb[col];
#pragma unroll
    for (int i = 0; i < F_IN; i++) a += xrow[i] * wrow[i];
    g_x[tid] = fmaxf(a, 0.f);
}

// ---------------- CSR build ------------------------------------------------
__global__ void zero_cnt_out_kernel(float* out) {
    int i = blockIdx.x * blockDim.x + threadIdx.x;
    if (i < N_NODES) g_cnt[i] = 0;
    if (i < 2 * HID) out[i] = 0.f;   // mean accum + max accum (x >= 0)
}

__global__ void zero_cnt_kernel() {
    int i = blockIdx.x * blockDim.x + threadIdx.x;
    if (i < N_NODES) g_cnt[i] = 0;
}

__global__ void count_kernel(const int* __restrict__ ei) {
    int e = blockIdx.x * blockDim.x + threadIdx.x;
    if (e < N_EDGES) atomicAdd(&g_cnt[ei[N_EDGES + e]], 1);
}

__device__ __forceinline__ int warp_incl_scan(int v) {
    int lane = threadIdx.x & 31;
#pragma unroll
    for (int off = 1; off < 32; off <<= 1) {
        int n = __shfl_up_sync(0xFFFFFFFFu, v, off);
        if (lane >= off) v += n;
    }
    return v;
}

__global__ void blocksum_kernel() {
    __shared__ int ws[SCAN_BLK / 32];
    int i = blockIdx.x * SCAN_BLK + threadIdx.x;
    int v = (i < N_NODES) ? g_cnt[i] : 0;
#pragma unroll
    for (int off = 16; off > 0; off >>= 1) v += __shfl_xor_sync(0xFFFFFFFFu, v, off);
    if ((threadIdx.x & 31) == 0) ws[threadIdx.x >> 5] = v;
    __syncthreads();
    if (threadIdx.x < 32) {
        int t = (threadIdx.x < SCAN_BLK / 32) ? ws[threadIdx.x] : 0;
#pragma unroll
        for (int off = 8; off > 0; off >>= 1) t += __shfl_xor_sync(0xFFFFFFFFu, t, off);
        if (threadIdx.x == 0) g_bsum[blockIdx.x] = t;
    }
}

__global__ void bsum_scan_kernel() {   // 1 block, 128 threads, scans 98 values
    __shared__ int ws[4];
    int tid = threadIdx.x;
    int v = (tid < NSCAN_BLKS) ? g_bsum[tid] : 0;
    int incl = warp_incl_scan(v);
    if ((tid & 31) == 31) ws[tid >> 5] = incl;
    __syncthreads();
    if (tid < 32) {
        int t = (tid < 4) ? ws[tid] : 0;
        t = warp_incl_scan(t);
        if (tid < 4) ws[tid] = t;
    }
    __syncthreads();
    int wid = tid >> 5;
    int excl = (wid ? ws[wid - 1] : 0) + incl - v;
    if (tid < NSCAN_BLKS) g_bsum[tid] = excl;
}

__global__ void rowptr_kernel() {
    __shared__ int ws[SCAN_BLK / 32];
    int tid = threadIdx.x;
    int i = blockIdx.x * SCAN_BLK + tid;
    int v = (i < N_NODES) ? g_cnt[i] : 0;
    int incl = warp_incl_scan(v);
    int wid = tid >> 5;
    if ((tid & 31) == 31) ws[wid] = incl;
    __syncthreads();
    if (tid < 32) {
        int t = (tid < SCAN_BLK / 32) ? ws[tid] : 0;
        t = warp_incl_scan(t);
        if (tid < SCAN_BLK / 32) ws[tid] = t;
    }
    __syncthreads();
    int base = g_bsum[blockIdx.x] + (wid ? ws[wid - 1] : 0);
    int excl = base + incl - v;
    if (i < N_NODES)      g_rowptr[i] = excl;
    if (i == N_NODES - 1) g_rowptr[N_NODES] = excl + v;
}

__global__ void scatter_kernel(const int* __restrict__ ei) {
    int e = blockIdx.x * blockDim.x + threadIdx.x;
    if (e >= N_EDGES) return;
    int src = ei[e];
    int dst = ei[N_EDGES + e];
    int pos = g_rowptr[dst] + atomicAdd(&g_cnt[dst], 1);
    g_csr_src[pos] = src;
}

// ---------------- node transform (one matrix per CTA): xo = x@W^T + b ------
// CTA: 64 nodes x 128 cols, 256 threads (8 warps x 8 nodes each).
// W transposed+padded in smem (67.6KB -> 3 CTAs/SM, 24 warps).
// x read directly from global via warp-uniform broadcast LDG.128 (rows are
// warp-private; smem staging was pure overhead).
#define BN        64
#define WT_STRIDE 132
#define TF_SMEM   (128 * WT_STRIDE * 4)   // 67584 bytes

__global__ __launch_bounds__(256, 3)
void transform_half_kernel(const float* __restrict__ Wlg,
                           const float* __restrict__ blg,
                           const float* __restrict__ Wrg,
                           const float* __restrict__ brg) {
    extern __shared__ float smem[];
    float* sW = smem;                       // [128][WT_STRIDE]  sW[k][o]

    int which = blockIdx.y;
    const float* Wg = which ? Wrg : Wlg;
    const float* bg = which ? brg : blg;
    float* xo = which ? g_xr : g_xl;

    int nbase = blockIdx.x * BN;
    for (int idx = threadIdx.x; idx < HID * HID; idx += 256) {
        int o = idx >> 7, k = idx & 127;
        sW[k * WT_STRIDE + o] = Wg[idx];
    }
    __syncthreads();

    int lane = threadIdx.x & 31;
    int wrp  = threadIdx.x >> 5;
    int col  = lane * 4;
    int n0   = wrp * 8;

    // warp-private x row pointers (clamped; stores are guarded below)
    const float* xrow[8];
#pragma unroll
    for (int j = 0; j < 8; j++) {
        int node = nbase + n0 + j;
        xrow[j] = &g_x[(node < N_NODES ? node : N_NODES - 1) * HID];
    }

    unsigned long long acc[8][2];
#pragma unroll
    for (int j = 0; j < 8; j++) { acc[j][0] = 0ull; acc[j][1] = 0ull; }

    for (int kq = 0; kq < 128; kq += 4) {
        float4 xq[8];
#pragma unroll
        for (int j = 0; j < 8; j++)
            xq[j] = *reinterpret_cast<const float4*>(xrow[j] + kq);  // broadcast LDG
        const float* xs = reinterpret_cast<const float*>(xq);
#pragma unroll
        for (int kk = 0; kk < 4; kk++) {
            int k = kq + kk;
            ulonglong2 w = *reinterpret_cast<const ulonglong2*>(&sW[k * WT_STRIDE + col]);
#pragma unroll
            for (int j = 0; j < 8; j++) {
                float xv = xs[j * 4 + kk];
                unsigned long long xp = pack2(xv, xv);
                ffma2(acc[j][0], xp, w.x);
                ffma2(acc[j][1], xp, w.y);
            }
        }
    }

    float4 b4 = *reinterpret_cast<const float4*>(&bg[col]);
#pragma unroll
    for (int j = 0; j < 8; j++) {
        int node = nbase + n0 + j;
        if (node < N_NODES) {
            float2 a0 = unpack2(acc[j][0]), a1 = unpack2(acc[j][1]);
            float4 o = {a0.x + b4.x, a0.y + b4.y, a1.x + b4.z, a1.y + b4.w};
            *reinterpret_cast<float4*>(&xo[(size_t)node * HID + col]) = o;
        }
    }
}

// ---------------- GATv2 aggregation: warp/node, dual-stream online softmax -
// lane = h*8 + i; lane owns channels [h*32 + i*4 .. +3] as float4.
__global__ __launch_bounds__(256)
void gat_agg_kernel(const float* __restrict__ att,
                    const float* __restrict__ bias,
                    int layer) {
    int warp = (blockIdx.x * blockDim.x + threadIdx.x) >> 5;
    int lane = threadIdx.x & 31;
    if (warp >= N_NODES) return;
    int node = warp;
    int h = lane >> 3;
    int i4 = (lane & 7) * 4;
    int chan = h * CDIM + i4;
    int base = node * HID + chan;

    float4 xr4 = *reinterpret_cast<const float4*>(&g_xr[base]);
    float4 at4 = *reinterpret_cast<const float4*>(&att[layer * HID + chan]);

    int beg = g_rowptr[node], end = g_rowptr[node + 1];
    int deg = end - beg;
    int nA  = (deg + 1) >> 1;
    int pB0 = beg + nA;

    float4 accA = {0,0,0,0}, accB = {0,0,0,0};
    float dA = 0.f, dB = 0.f, mA = -1e30f, mB = -1e30f;
    float4 xA = {0,0,0,0}, xB = {0,0,0,0};
    if (deg > 0)   xA = *reinterpret_cast<const float4*>(&g_xl[g_csr_src[beg] * HID + chan]);
    if (pB0 < end) xB = *reinterpret_cast<const float4*>(&g_xl[g_csr_src[pB0] * HID + chan]);
    const float NEG_INF = __int_as_float(0xff800000);

    for (int i = 0; i < nA; i++) {
        float4 cA = xA, cB = xB;
        bool hasB = (pB0 + i) < end;
        if (i + 1 < nA)        xA = *reinterpret_cast<const float4*>(&g_xl[g_csr_src[beg + i + 1] * HID + chan]);
        if (pB0 + i + 1 < end) xB = *reinterpret_cast<const float4*>(&g_xl[g_csr_src[pB0 + i + 1] * HID + chan]);

        float a0 = cA.x + xr4.x, a1 = cA.y + xr4.y, a2 = cA.z + xr4.z, a3 = cA.w + xr4.w;
        float b0 = cB.x + xr4.x, b1 = cB.y + xr4.y, b2 = cB.z + xr4.z, b3 = cB.w + xr4.w;
        a0 = (a0 > 0.f) ? a0 : 0.2f * a0;  b0 = (b0 > 0.f) ? b0 : 0.2f * b0;
        a1 = (a1 > 0.f) ? a1 : 0.2f * a1;  b1 = (b1 > 0.f) ? b1 : 0.2f * b1;
        a2 = (a2 > 0.f) ? a2 : 0.2f * a2;  b2 = (b2 > 0.f) ? b2 : 0.2f * b2;
        a3 = (a3 > 0.f) ? a3 : 0.2f * a3;  b3 = (b3 > 0.f) ? b3 : 0.2f * b3;
        float la = a0 * at4.x + a1 * at4.y + a2 * at4.z + a3 * at4.w;
        float lb = b0 * at4.x + b1 * at4.y + b2 * at4.z + b3 * at4.w;
        la += __shfl_xor_sync(0xFFFFFFFFu, la, 4);
        lb += __shfl_xor_sync(0xFFFFFFFFu, lb, 4);
        la += __shfl_xor_sync(0xFFFFFFFFu, la, 2);
        lb += __shfl_xor_sync(0xFFFFFFFFu, lb, 2);
        la += __shfl_xor_sync(0xFFFFFFFFu, la, 1);
        lb += __shfl_xor_sync(0xFFFFFFFFu, lb, 1);
        lb = hasB ? lb : NEG_INF;

        float nmA = fmaxf(mA, la);
        float scA = __expf(mA - nmA);
        float pa  = __expf(la - nmA);
        dA = dA * scA + pa;
        accA.x = accA.x * scA + pa * cA.x;
        accA.y = accA.y * scA + pa * cA.y;
        accA.z = accA.z * scA + pa * cA.z;
        accA.w = accA.w * scA + pa * cA.w;
        mA = nmA;

        float nmB = fmaxf(mB, lb);
        float scB = __expf(mB - nmB);
        float pb  = __expf(lb - nmB);
        dB = dB * scB + pb;
        accB.x = accB.x * scB + pb * cB.x;
        accB.y = accB.y * scB + pb * cB.y;
        accB.z = accB.z * scB + pb * cB.z;
        accB.w = accB.w * scB + pb * cB.w;
        mB = nmB;
    }

    // merge streams
    float nm = fmaxf(mA, mB);
    float sA = __expf(mA - nm), sB = __expf(mB - nm);
    float den = dA * sA + dB * sB;
    float4 acc;
    acc.x = accA.x * sA + accB.x * sB;
    acc.y = accA.y * sA + accB.y * sB;
    acc.z = accA.z * sA + accB.z * sB;
    acc.w = accA.w * sA + accB.w * sB;

    float inv = (den > 0.f) ? 1.f / den : 0.f;
    float4 b4 = *reinterpret_cast<const float4*>(&bias[layer * HID + chan]);
    float4 o;
    o.x = fmaxf(acc.x * inv + b4.x, 0.f);
    o.y = fmaxf(acc.y * inv + b4.y, 0.f);
    o.z = fmaxf(acc.z * inv + b4.z, 0.f);
    o.w = fmaxf(acc.w * inv + b4.w, 0.f);
    if (layer > 0) {
        float4 prev = *reinterpret_cast<const float4*>(&g_x[base]);
        o.x += prev.x; o.y += prev.y; o.z += prev.z; o.w += prev.w;
    }
    *reinterpret_cast<float4*>(&g_x[base]) = o;
}

// ---------------- epilogue: graph embedding + x copy (fused) ---------------
__global__ void reduce2_kernel(float* __restrict__ out) {
    int col = threadIdx.x;   // 128 threads
    float s = 0.f, mx = 0.f;
    for (int r = blockIdx.x; r < N_NODES; r += gridDim.x) {
        float v = g_x[r * HID + col];
        s += v;
        mx = fmaxf(mx, v);
        out[2 * HID + r * HID + col] = v;
    }
    atomicAdd(&out[col], s * (1.0f / N_NODES));
    atomicMax(reinterpret_cast<int*>(out) + HID + col, __float_as_int(mx));  // x >= 0
}

// ---------------- launch ---------------------------------------------------
extern "C" void kernel_launch(void* const* d_in, const int* in_sizes, int n_in,
                              void* d_out, int out_size) {
    const float* nf   = (const float*)d_in[0];
    const int*   ei   = (const int*)  d_in[1];
    const float* Wemb = (const float*)d_in[3];
    const float* bemb = (const float*)d_in[4];
    const float* Wl   = (const float*)d_in[5];
    const float* bl   = (const float*)d_in[6];
    const float* Wr   = (const float*)d_in[7];
    const float* br   = (const float*)d_in[8];
    const float* att  = (const float*)d_in[9];
    const float* bias = (const float*)d_in[10];
    float* out = (float*)d_out;

    cudaFuncSetAttribute(transform_half_kernel,
                         cudaFuncAttributeMaxDynamicSharedMemorySize, TF_SMEM);

    dim3 tf_grid((N_NODES + BN - 1) / BN, 2);

    // transform kernel at launch slot #4 so the fixed "-s 5 -c 1" ncu capture
    // lands on the dominant kernel.
    embed_kernel<<<(N_NODES * HID + 255) / 256, 256>>>(nf, Wemb, bemb);          // 1
    zero_cnt_out_kernel<<<(N_NODES + 255) / 256, 256>>>(out);                    // 2
    count_kernel<<<(N_EDGES + 255) / 256, 256>>>(ei);                            // 3
    transform_half_kernel<<<tf_grid, 256, TF_SMEM>>>(Wl, bl, Wr, br);            // 4 (layer 0)
    blocksum_kernel<<<NSCAN_BLKS, SCAN_BLK>>>();                                 // 5
    bsum_scan_kernel<<<1, 128>>>();                                              // 6
    rowptr_kernel<<<NSCAN_BLKS, SCAN_BLK>>>();                                   // 7
    zero_cnt_kernel<<<(N_NODES + 255) / 256, 256>>>();                           // 8
    scatter_kernel<<<(N_EDGES + 255) / 256, 256>>>(ei);                          // 9

    // GATv2 layers
    for (int l = 0; l < NLAYERS; l++) {
        if (l > 0)
            transform_half_kernel<<<tf_grid, 256, TF_SMEM>>>(
                Wl + l * HID * HID, bl + l * HID, Wr + l * HID * HID, br + l * HID);
        gat_agg_kernel<<<(N_NODES * 32 + 255) / 256, 256>>>(att, bias, l);
    }

    // outputs: [graph_mean(128) | graph_max(128) | x(50000*128)]
    reduce2_kernel<<<1024, HID>>>(out);
}

// round 16
// speedup vs baseline: 1.6530x; 1.1239x over previous
#include <cuda_runtime.h>
#include <math.h>

#define N_NODES 50000
#define N_EDGES 800000
#define F_IN    11
#define HID     128
#define HEADS   4
#define CDIM    32
#define NLAYERS 4

// ---------------- scratch (device globals; no allocation allowed) ----------
__device__ float g_x [N_NODES * HID];
__device__ float g_xl[N_NODES * HID];
__device__ float g_xr[N_NODES * HID];
__device__ int   g_rowptr[N_NODES + 1];
__device__ int   g_cnt[N_NODES];
__device__ int   g_csr_src[N_EDGES];

#define SCAN_BLK   512
#define NSCAN_BLKS ((N_NODES + SCAN_BLK - 1) / SCAN_BLK)   // 98
__device__ int g_bsum[NSCAN_BLKS];

// ---------------- f32x2 packed math helpers --------------------------------
__device__ __forceinline__ unsigned long long pack2(float x, float y) {
    unsigned long long r;
    asm("mov.b64 %0, {%1, %2};" : "=l"(r) : "f"(x), "f"(y));
    return r;
}
__device__ __forceinline__ float2 unpack2(unsigned long long v) {
    float2 r;
    asm("mov.b64 {%0, %1}, %2;" : "=f"(r.x), "=f"(r.y) : "l"(v));
    return r;
}
__device__ __forceinline__ void ffma2(unsigned long long& d,
                                      unsigned long long a,
                                      unsigned long long b) {
    asm("fma.rn.f32x2 %0, %1, %2, %0;" : "+l"(d) : "l"(a), "l"(b));
}

// ---------------- embedding: x = relu(nf @ W_emb^T + b_emb) ----------------
__global__ void embed_kernel(const float* __restrict__ nf,
                             const float* __restrict__ Wemb,
                             const float* __restrict__ bemb) {
    int tid = blockIdx.x * blockDim.x + threadIdx.x;
    if (tid >= N_NODES * HID) return;
    int node = tid >> 7;
    int col  = tid & 127;
    const float* xrow = nf + node * F_IN;
    const float* wrow = Wemb + col * F_IN;
    float a = bemb[col];
#pragma unroll
    for (int i = 0; i < F_IN; i++) a += xrow[i] * wrow[i];
    g_x[tid] = fmaxf(a, 0.f);
}

// ---------------- CSR build ------------------------------------------------
__global__ void zero_cnt_out_kernel(float* out) {
    int i = blockIdx.x * blockDim.x + threadIdx.x;
    if (i < N_NODES) g_cnt[i] = 0;
    if (i < 2 * HID) out[i] = 0.f;   // mean accum + max accum (x >= 0)
}

__global__ void zero_cnt_kernel() {
    int i = blockIdx.x * blockDim.x + threadIdx.x;
    if (i < N_NODES) g_cnt[i] = 0;
}

__global__ void count_kernel(const int* __restrict__ ei) {
    int e = blockIdx.x * blockDim.x + threadIdx.x;
    if (e < N_EDGES) atomicAdd(&g_cnt[ei[N_EDGES + e]], 1);
}

__device__ __forceinline__ int warp_incl_scan(int v) {
    int lane = threadIdx.x & 31;
#pragma unroll
    for (int off = 1; off < 32; off <<= 1) {
        int n = __shfl_up_sync(0xFFFFFFFFu, v, off);
        if (lane >= off) v += n;
    }
    return v;
}

__global__ void blocksum_kernel() {
    __shared__ int ws[SCAN_BLK / 32];
    int i = blockIdx.x * SCAN_BLK + threadIdx.x;
    int v = (i < N_NODES) ? g_cnt[i] : 0;
#pragma unroll
    for (int off = 16; off > 0; off >>= 1) v += __shfl_xor_sync(0xFFFFFFFFu, v, off);
    if ((threadIdx.x & 31) == 0) ws[threadIdx.x >> 5] = v;
    __syncthreads();
    if (threadIdx.x < 32) {
        int t = (threadIdx.x < SCAN_BLK / 32) ? ws[threadIdx.x] : 0;
#pragma unroll
        for (int off = 8; off > 0; off >>= 1) t += __shfl_xor_sync(0xFFFFFFFFu, t, off);
        if (threadIdx.x == 0) g_bsum[blockIdx.x] = t;
    }
}

__global__ void bsum_scan_kernel() {   // 1 block, 128 threads, scans 98 values
    __shared__ int ws[4];
    int tid = threadIdx.x;
    int v = (tid < NSCAN_BLKS) ? g_bsum[tid] : 0;
    int incl = warp_incl_scan(v);
    if ((tid & 31) == 31) ws[tid >> 5] = incl;
    __syncthreads();
    if (tid < 32) {
        int t = (tid < 4) ? ws[tid] : 0;
        t = warp_incl_scan(t);
        if (tid < 4) ws[tid] = t;
    }
    __syncthreads();
    int wid = tid >> 5;
    int excl = (wid ? ws[wid - 1] : 0) + incl - v;
    if (tid < NSCAN_BLKS) g_bsum[tid] = excl;
}

__global__ void rowptr_kernel() {
    __shared__ int ws[SCAN_BLK / 32];
    int tid = threadIdx.x;
    int i = blockIdx.x * SCAN_BLK + tid;
    int v = (i < N_NODES) ? g_cnt[i] : 0;
    int incl = warp_incl_scan(v);
    int wid = tid >> 5;
    if ((tid & 31) == 31) ws[wid] = incl;
    __syncthreads();
    if (tid < 32) {
        int t = (tid < SCAN_BLK / 32) ? ws[tid] : 0;
        t = warp_incl_scan(t);
        if (tid < SCAN_BLK / 32) ws[tid] = t;
    }
    __syncthreads();
    int base = g_bsum[blockIdx.x] + (wid ? ws[wid - 1] : 0);
    int excl = base + incl - v;
    if (i < N_NODES)      g_rowptr[i] = excl;
    if (i == N_NODES - 1) g_rowptr[N_NODES] = excl + v;
}

__global__ void scatter_kernel(const int* __restrict__ ei) {
    int e = blockIdx.x * blockDim.x + threadIdx.x;
    if (e >= N_EDGES) return;
    int src = ei[e];
    int dst = ei[N_EDGES + e];
    int pos = g_rowptr[dst] + atomicAdd(&g_cnt[dst], 1);
    g_csr_src[pos] = src;
}

// ---------------- persistent node transform: xo = x@W^T + b ----------------
// grid (148, 2): blockIdx.y selects L/R. Each CTA stages its W ONCE, then
// loops over 64-node x tiles (tile += gridDim.x). 99.6KB smem -> 2 CTAs/SM.
// Inner loop identical to the proven R13 half kernel.
#define BN        64
#define WT_STRIDE 132
#define NTILES    ((N_NODES + BN - 1) / BN)               // 782
#define TF_SMEM   ((128 * WT_STRIDE + BN * HID) * 4)      // 99584 bytes

__global__ __launch_bounds__(256, 2)
void transform_persist_kernel(const float* __restrict__ Wlg,
                              const float* __restrict__ blg,
                              const float* __restrict__ Wrg,
                              const float* __restrict__ brg) {
    extern __shared__ float smem[];
    float* sW = smem;                       // [128][WT_STRIDE]  sW[k][o]
    float* sx = smem + 128 * WT_STRIDE;     // [BN][128]

    int which = blockIdx.y;
    const float* Wg = which ? Wrg : Wlg;
    const float* bg = which ? brg : blg;
    float* xo = which ? g_xr : g_xl;

    // stage W once for this CTA's lifetime
    for (int idx = threadIdx.x; idx < HID * HID; idx += 256) {
        int o = idx >> 7, k = idx & 127;
        sW[k * WT_STRIDE + o] = Wg[idx];
    }

    int lane = threadIdx.x & 31;
    int wrp  = threadIdx.x >> 5;
    int col  = lane * 4;
    int n0   = wrp * 8;
    float4 b4 = *reinterpret_cast<const float4*>(&bg[col]);

    for (int tile = blockIdx.x; tile < NTILES; tile += gridDim.x) {
        int nbase = tile * BN;

        // stage x tile (float4 granularity)
        for (int idx = threadIdx.x; idx < BN * (HID / 4); idx += 256) {
            int row = idx >> 5, c4 = idx & 31;
            int node = nbase + row;
            float4 v = {0.f, 0.f, 0.f, 0.f};
            if (node < N_NODES)
                v = *reinterpret_cast<const float4*>(&g_x[node * HID + c4 * 4]);
            *reinterpret_cast<float4*>(&sx[row * HID + c4 * 4]) = v;
        }
        __syncthreads();   // first iteration: also covers the W staging

        unsigned long long acc[8][2];
#pragma unroll
        for (int j = 0; j < 8; j++) { acc[j][0] = 0ull; acc[j][1] = 0ull; }

        for (int kq = 0; kq < 128; kq += 4) {
            float4 xq[8];
#pragma unroll
            for (int j = 0; j < 8; j++)
                xq[j] = *reinterpret_cast<const float4*>(&sx[(n0 + j) * HID + kq]);
            const float* xs = reinterpret_cast<const float*>(xq);
#pragma unroll
            for (int kk = 0; kk < 4; kk++) {
                int k = kq + kk;
                ulonglong2 w = *reinterpret_cast<const ulonglong2*>(&sW[k * WT_STRIDE + col]);
#pragma unroll
                for (int j = 0; j < 8; j++) {
                    float xv = xs[j * 4 + kk];
                    unsigned long long xp = pack2(xv, xv);
                    ffma2(acc[j][0], xp, w.x);
                    ffma2(acc[j][1], xp, w.y);
                }
            }
        }

#pragma unroll
        for (int j = 0; j < 8; j++) {
            int node = nbase + n0 + j;
            if (node < N_NODES) {
                float2 a0 = unpack2(acc[j][0]), a1 = unpack2(acc[j][1]);
                float4 o = {a0.x + b4.x, a0.y + b4.y, a1.x + b4.z, a1.y + b4.w};
                *reinterpret_cast<float4*>(&xo[(size_t)node * HID + col]) = o;
            }
        }
        __syncthreads();   // sx may be overwritten next iteration
    }
}

// ---------------- GATv2 aggregation: warp/node, dual-stream online softmax -
// lane = h*8 + i; lane owns channels [h*32 + i*4 .. +3] as float4.
__global__ __launch_bounds__(256)
void gat_agg_kernel(const float* __restrict__ att,
                    const float* __restrict__ bias,
                    int layer) {
    int warp = (blockIdx.x * blockDim.x + threadIdx.x) >> 5;
    int lane = threadIdx.x & 31;
    if (warp >= N_NODES) return;
    int node = warp;
    int h = lane >> 3;
    int i4 = (lane & 7) * 4;
    int chan = h * CDIM + i4;
    int base = node * HID + chan;

    float4 xr4 = *reinterpret_cast<const float4*>(&g_xr[base]);
    float4 at4 = *reinterpret_cast<const float4*>(&att[layer * HID + chan]);

    int beg = g_rowptr[node], end = g_rowptr[node + 1];
    int deg = end - beg;
    int nA  = (deg + 1) >> 1;
    int pB0 = beg + nA;

    float4 accA = {0,0,0,0}, accB = {0,0,0,0};
    float dA = 0.f, dB = 0.f, mA = -1e30f, mB = -1e30f;
    float4 xA = {0,0,0,0}, xB = {0,0,0,0};
    if (deg > 0)   xA = *reinterpret_cast<const float4*>(&g_xl[g_csr_src[beg] * HID + chan]);
    if (pB0 < end) xB = *reinterpret_cast<const float4*>(&g_xl[g_csr_src[pB0] * HID + chan]);
    const float NEG_INF = __int_as_float(0xff800000);

    for (int i = 0; i < nA; i++) {
        float4 cA = xA, cB = xB;
        bool hasB = (pB0 + i) < end;
        if (i + 1 < nA)        xA = *reinterpret_cast<const float4*>(&g_xl[g_csr_src[beg + i + 1] * HID + chan]);
        if (pB0 + i + 1 < end) xB = *reinterpret_cast<const float4*>(&g_xl[g_csr_src[pB0 + i + 1] * HID + chan]);

        float a0 = cA.x + xr4.x, a1 = cA.y + xr4.y, a2 = cA.z + xr4.z, a3 = cA.w + xr4.w;
        float b0 = cB.x + xr4.x, b1 = cB.y + xr4.y, b2 = cB.z + xr4.z, b3 = cB.w + xr4.w;
        a0 = (a0 > 0.f) ? a0 : 0.2f * a0;  b0 = (b0 > 0.f) ? b0 : 0.2f * b0;
        a1 = (a1 > 0.f) ? a1 : 0.2f * a1;  b1 = (b1 > 0.f) ? b1 : 0.2f * b1;
        a2 = (a2 > 0.f) ? a2 : 0.2f * a2;  b2 = (b2 > 0.f) ? b2 : 0.2f * b2;
        a3 = (a3 > 0.f) ? a3 : 0.2f * a3;  b3 = (b3 > 0.f) ? b3 : 0.2f * b3;
        float la = a0 * at4.x + a1 * at4.y + a2 * at4.z + a3 * at4.w;
        float lb = b0 * at4.x + b1 * at4.y + b2 * at4.z + b3 * at4.w;
        la += __shfl_xor_sync(0xFFFFFFFFu, la, 4);
        lb += __shfl_xor_sync(0xFFFFFFFFu, lb, 4);
        la += __shfl_xor_sync(0xFFFFFFFFu, la, 2);
        lb += __shfl_xor_sync(0xFFFFFFFFu, lb, 2);
        la += __shfl_xor_sync(0xFFFFFFFFu, la, 1);
        lb += __shfl_xor_sync(0xFFFFFFFFu, lb, 1);
        lb = hasB ? lb : NEG_INF;

        float nmA = fmaxf(mA, la);
        float scA = __expf(mA - nmA);
        float pa  = __expf(la - nmA);
        dA = dA * scA + pa;
        accA.x = accA.x * scA + pa * cA.x;
        accA.y = accA.y * scA + pa * cA.y;
        accA.z = accA.z * scA + pa * cA.z;
        accA.w = accA.w * scA + pa * cA.w;
        mA = nmA;

        float nmB = fmaxf(mB, lb);
        float scB = __expf(mB - nmB);
        float pb  = __expf(lb - nmB);
        dB = dB * scB + pb;
        accB.x = accB.x * scB + pb * cB.x;
        accB.y = accB.y * scB + pb * cB.y;
        accB.z = accB.z * scB + pb * cB.z;
        accB.w = accB.w * scB + pb * cB.w;
        mB = nmB;
    }

    // merge streams
    float nm = fmaxf(mA, mB);
    float sA = __expf(mA - nm), sB = __expf(mB - nm);
    float den = dA * sA + dB * sB;
    float4 acc;
    acc.x = accA.x * sA + accB.x * sB;
    acc.y = accA.y * sA + accB.y * sB;
    acc.z = accA.z * sA + accB.z * sB;
    acc.w = accA.w * sA + accB.w * sB;

    float inv = (den > 0.f) ? 1.f / den : 0.f;
    float4 b4 = *reinterpret_cast<const float4*>(&bias[layer * HID + chan]);
    float4 o;
    o.x = fmaxf(acc.x * inv + b4.x, 0.f);
    o.y = fmaxf(acc.y * inv + b4.y, 0.f);
    o.z = fmaxf(acc.z * inv + b4.z, 0.f);
    o.w = fmaxf(acc.w * inv + b4.w, 0.f);
    if (layer > 0) {
        float4 prev = *reinterpret_cast<const float4*>(&g_x[base]);
        o.x += prev.x; o.y += prev.y; o.z += prev.z; o.w += prev.w;
    }
    *reinterpret_cast<float4*>(&g_x[base]) = o;
}

// ---------------- epilogue: graph embedding + x copy (fused) ---------------
__global__ void reduce2_kernel(float* __restrict__ out) {
    int col = threadIdx.x;   // 128 threads
    float s = 0.f, mx = 0.f;
    for (int r = blockIdx.x; r < N_NODES; r += gridDim.x) {
        float v = g_x[r * HID + col];
        s += v;
        mx = fmaxf(mx, v);
        out[2 * HID + r * HID + col] = v;
    }
    atomicAdd(&out[col], s * (1.0f / N_NODES));
    atomicMax(reinterpret_cast<int*>(out) + HID + col, __float_as_int(mx));  // x >= 0
}

// ---------------- launch ---------------------------------------------------
extern "C" void kernel_launch(void* const* d_in, const int* in_sizes, int n_in,
                              void* d_out, int out_size) {
    const float* nf   = (const float*)d_in[0];
    const int*   ei   = (const int*)  d_in[1];
    const float* Wemb = (const float*)d_in[3];
    const float* bemb = (const float*)d_in[4];
    const float* Wl   = (const float*)d_in[5];
    const float* bl   = (const float*)d_in[6];
    const float* Wr   = (const float*)d_in[7];
    const float* br   = (const float*)d_in[8];
    const float* att  = (const float*)d_in[9];
    const float* bias = (const float*)d_in[10];
    float* out = (float*)d_out;

    cudaFuncSetAttribute(transform_persist_kernel,
                         cudaFuncAttributeMaxDynamicSharedMemorySize, TF_SMEM);

    dim3 tf_grid(148, 2);   // persistent: 2 CTAs/SM resident, W staged once

    // transform kernel at launch slot #4 so the fixed "-s 5 -c 1" ncu capture
    // lands on the dominant kernel.
    embed_kernel<<<(N_NODES * HID + 255) / 256, 256>>>(nf, Wemb, bemb);          // 1
    zero_cnt_out_kernel<<<(N_NODES + 255) / 256, 256>>>(out);                    // 2
    count_kernel<<<(N_EDGES + 255) / 256, 256>>>(ei);                            // 3
    transform_persist_kernel<<<tf_grid, 256, TF_SMEM>>>(Wl, bl, Wr, br);         // 4 (layer 0)
    blocksum_kernel<<<NSCAN_BLKS, SCAN_BLK>>>();                                 // 5
    bsum_scan_kernel<<<1, 128>>>();                                              // 6
    rowptr_kernel<<<NSCAN_BLKS, SCAN_BLK>>>();                                   // 7
    zero_cnt_kernel<<<(N_NODES + 255) / 256, 256>>>();                           // 8
    scatter_kernel<<<(N_EDGES + 255) / 256, 256>>>(ei);                          // 9

    // GATv2 layers
    for (int l = 0; l < NLAYERS; l++) {
        if (l > 0)
            transform_persist_kernel<<<tf_grid, 256, TF_SMEM>>>(
                Wl + l * HID * HID, bl + l * HID, Wr + l * HID * HID, br + l * HID);
        gat_agg_kernel<<<(N_NODES * 32 + 255) / 256, 256>>>(att, bias, l);
    }

    // outputs: [graph_mean(128) | graph_max(128) | x(50000*128)]
    reduce2_kernel<<<1024, HID>>>(out);
}